// round 11
// baseline (speedup 1.0000x reference)
#include <cuda_runtime.h>

#define SS 512
#define EE 8
#define FF 4
#define FH 8   // F * num_heads

// Batch-independent precomputed cross-attention query-side terms:
// score[f,h,s] = x[s,:] . g_A[f*2+h,:] + g_c[f*2+h]
__device__ float g_A[FH][EE];
__device__ float g_c[FH];

__global__ void precompute_kernel(const float* __restrict__ Q,
                                  const float* __restrict__ sa_w_in,
                                  const float* __restrict__ sa_b_in,
                                  const float* __restrict__ sa_w_out,
                                  const float* __restrict__ sa_b_out,
                                  const float* __restrict__ ca_w_in,
                                  const float* __restrict__ ca_b_in) {
    float qh[FF][EE], kh[FF][EE], vh[FF][EE];
    for (int f = 0; f < FF; f++)
        for (int ep = 0; ep < EE; ep++) {
            float aq = sa_b_in[ep], ak = sa_b_in[8 + ep], av = sa_b_in[16 + ep];
            for (int e = 0; e < EE; e++) {
                float qe = Q[f * EE + e];
                aq += qe * sa_w_in[ep * EE + e];
                ak += qe * sa_w_in[(8 + ep) * EE + e];
                av += qe * sa_w_in[(16 + ep) * EE + e];
            }
            qh[f][ep] = aq; kh[f][ep] = ak; vh[f][ep] = av;
        }
    float ctx[FF][EE];
    for (int h = 0; h < 2; h++)
        for (int f = 0; f < FF; f++) {
            float sc[FF];
            float mx = -1e30f;
            for (int m = 0; m < FF; m++) {
                float s = 0.f;
                for (int d = 0; d < 4; d++) s += qh[f][h * 4 + d] * kh[m][h * 4 + d];
                s *= 0.5f;
                sc[m] = s;
                mx = fmaxf(mx, s);
            }
            float sum = 0.f;
            for (int m = 0; m < FF; m++) { sc[m] = expf(sc[m] - mx); sum += sc[m]; }
            for (int d = 0; d < 4; d++) {
                float a = 0.f;
                for (int m = 0; m < FF; m++) a += sc[m] * vh[m][h * 4 + d];
                ctx[f][h * 4 + d] = a / sum;
            }
        }
    float qu[FF][EE];
    for (int f = 0; f < FF; f++)
        for (int ep = 0; ep < EE; ep++) {
            float a = sa_b_out[ep];
            for (int e = 0; e < EE; e++) a += ctx[f][e] * sa_w_out[ep * EE + e];
            qu[f][ep] = a;
        }
    float qc[FF][EE];
    for (int f = 0; f < FF; f++)
        for (int ep = 0; ep < EE; ep++) {
            float a = ca_b_in[ep];
            for (int e = 0; e < EE; e++) a += qu[f][e] * ca_w_in[ep * EE + e];
            qc[f][ep] = a * 0.5f;
        }
    for (int f = 0; f < FF; f++)
        for (int h = 0; h < 2; h++) {
            float c = 0.f;
            for (int d = 0; d < 4; d++) c += qc[f][h * 4 + d] * ca_b_in[8 + h * 4 + d];
            g_c[f * 2 + h] = c;
            for (int e = 0; e < EE; e++) {
                float a = 0.f;
                for (int d = 0; d < 4; d++) a += qc[f][h * 4 + d] * ca_w_in[(8 + h * 4 + d) * EE + e];
                g_A[f * 2 + h][e] = a;
            }
        }
}

union F2U { float2 f; unsigned long long u; };

// packed dual-fp32 FMA (FFMA2) — only reachable via PTX fma.rn.f32x2
__device__ __forceinline__ float2 ffma2(float2 a, float2 b, float2 c) {
    F2U A, B, C, D;
    A.f = a; B.f = b; C.f = c;
    asm("fma.rn.f32x2 %0, %1, %2, %3;" : "=l"(D.u) : "l"(A.u), "l"(B.u), "l"(C.u));
    return D.f;
}

// Split-payload warp reduction of 9 values across 32 lanes: 12 SHFL total.
// After the call, the lane's v[0] holds the full-warp sum of ONE entry
// (entry index = 'start' computed by the caller, valid on even lanes with nreal>0).
__device__ __forceinline__ float warp_reduce9(float v[9]) {
    const int lane = threadIdx.x & 31;
    bool hi = (lane & 16);
#pragma unroll
    for (int i = 0; i < 5; i++) {
        float up = (i + 5 < 9) ? v[i + 5] : 0.f;
        float send = hi ? v[i] : up;
        float t = __shfl_xor_sync(~0u, send, 16);
        v[i] = (hi ? up : v[i]) + t;
    }
    hi = (lane & 8);
#pragma unroll
    for (int i = 0; i < 3; i++) {
        float up = (i + 3 < 5) ? v[i + 3] : 0.f;
        float send = hi ? v[i] : up;
        float t = __shfl_xor_sync(~0u, send, 8);
        v[i] = (hi ? up : v[i]) + t;
    }
    hi = (lane & 4);
#pragma unroll
    for (int i = 0; i < 2; i++) {
        float up = (i + 2 < 3) ? v[i + 2] : 0.f;
        float send = hi ? v[i] : up;
        float t = __shfl_xor_sync(~0u, send, 4);
        v[i] = (hi ? up : v[i]) + t;
    }
    hi = (lane & 2);
    {
        float send = hi ? v[0] : v[1];
        float t = __shfl_xor_sync(~0u, send, 2);
        v[0] = (hi ? v[1] : v[0]) + t;
    }
    v[0] += __shfl_xor_sync(~0u, v[0], 1);
    return v[0];
}

__global__ __launch_bounds__(256, 4) void afs_main_kernel(
    const float* __restrict__ x,
    const float* __restrict__ r_b2,
    float* __restrict__ outv, float* __restrict__ sim,
    const float* __restrict__ ca_w_in, const float* __restrict__ ca_b_in,
    const float* __restrict__ ca_w_out, const float* __restrict__ ca_b_out,
    const float* __restrict__ r_w1, const float* __restrict__ r_b1,
    const float* __restrict__ r_w2)
{
    __shared__ float pacc[8][96];       // [src warp][fh*12 + k], k<9 used
    __shared__ float red[80];           // combined entries (72 / 36)
    __shared__ float2 sA2[8][8];        // A duplicated for FFMA2
    __shared__ float2 scc2[8];
    __shared__ float2 sqc2[32];         // Q_cross duplicated
    __shared__ float swv[8][8];
    __shared__ float sbv[8];
    __shared__ float swo[8][8];
    __shared__ float sbo[8];
    __shared__ float sctx[32];
    __shared__ float sfin[32];
    __shared__ float srw1[16 * 33];     // padded stride 33
    __shared__ float srb1[16];
    __shared__ float srw2[16];
    __shared__ float sb2;

    const int tid = threadIdx.x;
    const int b = blockIdx.x;
    const int w = tid >> 5, lane = tid & 31;

    // ---- owned-entry bookkeeping for warp_reduce9 ----
    int start = 0, nreal = 9;
    if (lane & 16) { start += 5; nreal -= 5; } else nreal = 5;
    if (lane & 8)  { start += 3; nreal -= 3; } else nreal = (nreal < 3 ? nreal : 3);
    if (lane & 4)  { start += 2; nreal -= 2; } else nreal = (nreal < 2 ? nreal : 2);
    if (lane & 2)  { start += 1; nreal -= 1; } else nreal = (nreal < 1 ? nreal : 1);
    const bool wvalid = (nreal > 0) && !(lane & 1);

    // ---- load x rows s=tid and s=tid+256; keep packed (x0[e], x1[e]) ----
    const float4* __restrict__ xin = (const float4*)(x + (size_t)b * (SS * EE));
    float2 xp[8];
    {
        float4 a0 = xin[2 * tid],         a1 = xin[2 * tid + 1];
        float4 b0 = xin[2 * (tid + 256)], b1 = xin[2 * (tid + 256) + 1];
        xp[0] = make_float2(a0.x, b0.x); xp[1] = make_float2(a0.y, b0.y);
        xp[2] = make_float2(a0.z, b0.z); xp[3] = make_float2(a0.w, b0.w);
        xp[4] = make_float2(a1.x, b1.x); xp[5] = make_float2(a1.y, b1.y);
        xp[6] = make_float2(a1.z, b1.z); xp[7] = make_float2(a1.w, b1.w);
    }

    // ---- small weights to smem (A and c stored value-duplicated) ----
    if (tid < 64)       { float v = ((const float*)g_A)[tid]; ((float2*)sA2)[tid] = make_float2(v, v); }
    else if (tid < 72)  { float v = g_c[tid - 64]; scc2[tid - 64] = make_float2(v, v); }
    else if (tid < 136) ((float*)swv)[tid - 72]  = ca_w_in[16 * EE + (tid - 72)];
    else if (tid < 144) sbv[tid - 136]           = ca_b_in[16 + (tid - 136)];
    else if (tid < 208) ((float*)swo)[tid - 144] = ca_w_out[tid - 144];
    else if (tid < 216) sbo[tid - 208]           = ca_b_out[tid - 208];
    else if (tid < 232) srb1[tid - 216]          = r_b1[tid - 216];
    else if (tid < 248) srw2[tid - 232]          = r_w2[tid - 232];
    else if (tid == 248) sb2                     = r_b2[0];
#pragma unroll
    for (int i = tid; i < 512; i += 256) srw1[(i >> 5) * 33 + (i & 31)] = r_w1[i];
    __syncthreads();

    // ---- P1+P3: packed scores -> exp (no max; bounded) -> partials -> reduce ----
#pragma unroll
    for (int fh = 0; fh < 8; fh++) {
        float2 acc = scc2[fh];
#pragma unroll
        for (int e = 0; e < 8; e++) acc = ffma2(sA2[fh][e], xp[e], acc);
        float w0 = __expf(acc.x);
        float w1 = __expf(acc.y);
        float q[9];
#pragma unroll
        for (int e = 0; e < 8; e++) q[e] = fmaf(w0, xp[e].x, w1 * xp[e].y);
        q[8] = w0 + w1;
        float r = warp_reduce9(q);
        if (wvalid) pacc[w][fh * 12 + start] = r;
    }
    __syncthreads();

    // ---- combine 8 warp-partials in parallel: warp w handles fh=w ----
    if (lane < 9) {
        float s = 0.f;
#pragma unroll
        for (int p = 0; p < 8; p++) s += pacc[p][w * 12 + lane];
        red[w * 9 + lane] = s;
    }
    __syncthreads();

    // ---- P5: warp 0: ctx -> Q_cross (duplicated for packed use) ----
    if (w == 0) {
        {
            int f = lane >> 3, r = lane & 7;
            int fh = f * 2 + (r >> 2);
            float inv = 1.0f / red[fh * 9 + 8];
            float a = 0.f;
#pragma unroll
            for (int e = 0; e < 8; e++) a += red[fh * 9 + e] * swv[r][e];
            sctx[lane] = a * inv + sbv[r];
        }
        __syncwarp();
        {
            int f = lane >> 3, ep = lane & 7;
            float a = sbo[ep];
#pragma unroll
            for (int e = 0; e < 8; e++) a += sctx[f * 8 + e] * swo[ep][e];
            sqc2[f * 8 + ep] = make_float2(a, a);
        }
    }
    __syncthreads();

    // ---- P6+P7: packed similarity -> gmem; exp -> partials -> reduce ----
    float* __restrict__ simo = sim + (size_t)b * (FF * SS);
#pragma unroll
    for (int f = 0; f < 4; f++) {
        float2 acc = make_float2(0.f, 0.f);
#pragma unroll
        for (int e = 0; e < 8; e++) acc = ffma2(sqc2[f * 8 + e], xp[e], acc);
        simo[f * SS + tid]       = acc.x;
        simo[f * SS + tid + 256] = acc.y;
        float w0 = __expf(acc.x);
        float w1 = __expf(acc.y);
        float q[9];
#pragma unroll
        for (int e = 0; e < 8; e++) q[e] = fmaf(w0, xp[e].x, w1 * xp[e].y);
        q[8] = w0 + w1;
        float r = warp_reduce9(q);
        if (wvalid) pacc[w][f * 12 + start] = r;
    }
    __syncthreads();

    // ---- combine: warps 0-3 handle f=w ----
    if (w < 4 && lane < 9) {
        float s = 0.f;
#pragma unroll
        for (int p = 0; p < 8; p++) s += pacc[p][w * 12 + lane];
        red[w * 9 + lane] = s;
    }
    __syncthreads();

    // ---- P8: warp 0: final factors + MLP head ----
    if (w == 0) {
        {
            int f = lane >> 3, e = lane & 7;
            sfin[lane] = red[f * 9 + e] / red[f * 9 + 8];
        }
        __syncwarp();
        float v = 0.f;
        if (lane < 16) {
            float a = srb1[lane];
#pragma unroll
            for (int j = 0; j < 32; j++) a += sfin[j] * srw1[lane * 33 + j];
            v = fmaxf(a, 0.f) * srw2[lane];
        }
#pragma unroll
        for (int o = 16; o > 0; o >>= 1) v += __shfl_xor_sync(~0u, v, o);
        if (lane == 0) outv[b] = v + sb2;
    }
}

extern "C" void kernel_launch(void* const* d_in, const int* in_sizes, int n_in,
                              void* d_out, int out_size) {
    const float* x        = (const float*)d_in[0];
    const float* Q        = (const float*)d_in[1];
    const float* sa_w_in  = (const float*)d_in[2];
    const float* sa_b_in  = (const float*)d_in[3];
    const float* sa_w_out = (const float*)d_in[4];
    const float* sa_b_out = (const float*)d_in[5];
    const float* ca_w_in  = (const float*)d_in[6];
    const float* ca_b_in  = (const float*)d_in[7];
    const float* ca_w_out = (const float*)d_in[8];
    const float* ca_b_out = (const float*)d_in[9];
    const float* r_w1     = (const float*)d_in[10];
    const float* r_b1     = (const float*)d_in[11];
    const float* r_w2     = (const float*)d_in[12];
    const float* r_b2     = (const float*)d_in[13];

    int B = in_sizes[0] / (SS * EE);
    float* outv = (float*)d_out;          // [B] first return value
    float* sim  = outv + B;               // [B, F, S] second return value

    precompute_kernel<<<1, 1>>>(Q, sa_w_in, sa_b_in, sa_w_out, sa_b_out, ca_w_in, ca_b_in);
    afs_main_kernel<<<B, 256>>>(x, r_b2, outv, sim,
                                ca_w_in, ca_b_in, ca_w_out, ca_b_out,
                                r_w1, r_b1, r_w2);
}

// round 12
// speedup vs baseline: 1.5049x; 1.5049x over previous
#include <cuda_runtime.h>

#define SS 512
#define EE 8
#define FF 4
#define FH 8   // F * num_heads
#define NT 128 // threads per block
#define NR 4   // s-rows per thread

// Batch-independent precomputed cross-attention query-side terms:
// score[f,h,s] = x[s,:] . g_A[f*2+h,:] + g_c[f*2+h]
__device__ float g_A[FH][EE];
__device__ float g_c[FH];

__global__ void precompute_kernel(const float* __restrict__ Q,
                                  const float* __restrict__ sa_w_in,
                                  const float* __restrict__ sa_b_in,
                                  const float* __restrict__ sa_w_out,
                                  const float* __restrict__ sa_b_out,
                                  const float* __restrict__ ca_w_in,
                                  const float* __restrict__ ca_b_in) {
    float qh[FF][EE], kh[FF][EE], vh[FF][EE];
    for (int f = 0; f < FF; f++)
        for (int ep = 0; ep < EE; ep++) {
            float aq = sa_b_in[ep], ak = sa_b_in[8 + ep], av = sa_b_in[16 + ep];
            for (int e = 0; e < EE; e++) {
                float qe = Q[f * EE + e];
                aq += qe * sa_w_in[ep * EE + e];
                ak += qe * sa_w_in[(8 + ep) * EE + e];
                av += qe * sa_w_in[(16 + ep) * EE + e];
            }
            qh[f][ep] = aq; kh[f][ep] = ak; vh[f][ep] = av;
        }
    float ctx[FF][EE];
    for (int h = 0; h < 2; h++)
        for (int f = 0; f < FF; f++) {
            float sc[FF];
            float mx = -1e30f;
            for (int m = 0; m < FF; m++) {
                float s = 0.f;
                for (int d = 0; d < 4; d++) s += qh[f][h * 4 + d] * kh[m][h * 4 + d];
                s *= 0.5f;
                sc[m] = s;
                mx = fmaxf(mx, s);
            }
            float sum = 0.f;
            for (int m = 0; m < FF; m++) { sc[m] = expf(sc[m] - mx); sum += sc[m]; }
            for (int d = 0; d < 4; d++) {
                float a = 0.f;
                for (int m = 0; m < FF; m++) a += sc[m] * vh[m][h * 4 + d];
                ctx[f][h * 4 + d] = a / sum;
            }
        }
    float qu[FF][EE];
    for (int f = 0; f < FF; f++)
        for (int ep = 0; ep < EE; ep++) {
            float a = sa_b_out[ep];
            for (int e = 0; e < EE; e++) a += ctx[f][e] * sa_w_out[ep * EE + e];
            qu[f][ep] = a;
        }
    float qc[FF][EE];
    for (int f = 0; f < FF; f++)
        for (int ep = 0; ep < EE; ep++) {
            float a = ca_b_in[ep];
            for (int e = 0; e < EE; e++) a += qu[f][e] * ca_w_in[ep * EE + e];
            qc[f][ep] = a * 0.5f;
        }
    for (int f = 0; f < FF; f++)
        for (int h = 0; h < 2; h++) {
            float c = 0.f;
            for (int d = 0; d < 4; d++) c += qc[f][h * 4 + d] * ca_b_in[8 + h * 4 + d];
            g_c[f * 2 + h] = c;
            for (int e = 0; e < EE; e++) {
                float a = 0.f;
                for (int d = 0; d < 4; d++) a += qc[f][h * 4 + d] * ca_w_in[(8 + h * 4 + d) * EE + e];
                g_A[f * 2 + h][e] = a;
            }
        }
}

// Split-payload warp reduction of 9 values across 32 lanes: 12 SHFL total.
// After the call, the lane's v[0] holds the full-warp sum of ONE entry
// (entry index = 'start' computed by the caller, valid on even lanes with nreal>0).
__device__ __forceinline__ float warp_reduce9(float v[9]) {
    const int lane = threadIdx.x & 31;
    bool hi = (lane & 16);
#pragma unroll
    for (int i = 0; i < 5; i++) {
        float up = (i + 5 < 9) ? v[i + 5] : 0.f;
        float send = hi ? v[i] : up;
        float t = __shfl_xor_sync(~0u, send, 16);
        v[i] = (hi ? up : v[i]) + t;
    }
    hi = (lane & 8);
#pragma unroll
    for (int i = 0; i < 3; i++) {
        float up = (i + 3 < 5) ? v[i + 3] : 0.f;
        float send = hi ? v[i] : up;
        float t = __shfl_xor_sync(~0u, send, 8);
        v[i] = (hi ? up : v[i]) + t;
    }
    hi = (lane & 4);
#pragma unroll
    for (int i = 0; i < 2; i++) {
        float up = (i + 2 < 3) ? v[i + 2] : 0.f;
        float send = hi ? v[i] : up;
        float t = __shfl_xor_sync(~0u, send, 4);
        v[i] = (hi ? up : v[i]) + t;
    }
    hi = (lane & 2);
    {
        float send = hi ? v[0] : v[1];
        float t = __shfl_xor_sync(~0u, send, 2);
        v[0] = (hi ? v[1] : v[0]) + t;
    }
    v[0] += __shfl_xor_sync(~0u, v[0], 1);
    return v[0];
}

__global__ __launch_bounds__(NT, 6) void afs_main_kernel(
    const float* __restrict__ x,
    const float* __restrict__ r_b2,
    float* __restrict__ outv, float* __restrict__ sim,
    const float* __restrict__ ca_w_in, const float* __restrict__ ca_b_in,
    const float* __restrict__ ca_w_out, const float* __restrict__ ca_b_out,
    const float* __restrict__ r_w1, const float* __restrict__ r_b1,
    const float* __restrict__ r_w2)
{
    __shared__ float pacc[4][96];       // [src warp][fh*12 + k], k<9 used
    __shared__ float red[80];           // combined entries (72 / 36)
    __shared__ float sA[8][8];
    __shared__ float scc[8];
    __shared__ float sqc[32];
    __shared__ float swv[8][8];
    __shared__ float sbv[8];
    __shared__ float swo[8][8];
    __shared__ float sbo[8];
    __shared__ float sctx[32];
    __shared__ float sfin[32];
    __shared__ float srw1[16 * 33];     // padded stride 33
    __shared__ float srb1[16];
    __shared__ float srw2[16];
    __shared__ float sb2;

    const int tid = threadIdx.x;
    const int b = blockIdx.x;
    const int w = tid >> 5, lane = tid & 31;

    // ---- owned-entry bookkeeping for warp_reduce9 ----
    int start = 0, nreal = 9;
    if (lane & 16) { start += 5; nreal -= 5; } else nreal = 5;
    if (lane & 8)  { start += 3; nreal -= 3; } else nreal = (nreal < 3 ? nreal : 3);
    if (lane & 4)  { start += 2; nreal -= 2; } else nreal = (nreal < 2 ? nreal : 2);
    if (lane & 2)  { start += 1; nreal -= 1; } else nreal = (nreal < 1 ? nreal : 1);
    const bool wvalid = (nreal > 0) && !(lane & 1);

    // ---- load x rows s = tid + 128*r, r=0..3, into registers ----
    const float4* __restrict__ xin = (const float4*)(x + (size_t)b * (SS * EE));
    float xr[NR][EE];
#pragma unroll
    for (int r = 0; r < NR; r++) {
        float4 a0 = xin[2 * (tid + NT * r)];
        float4 a1 = xin[2 * (tid + NT * r) + 1];
        xr[r][0] = a0.x; xr[r][1] = a0.y; xr[r][2] = a0.z; xr[r][3] = a0.w;
        xr[r][4] = a1.x; xr[r][5] = a1.y; xr[r][6] = a1.z; xr[r][7] = a1.w;
    }

    // ---- small weights to smem (249 scalars, two strided passes) ----
#pragma unroll
    for (int i = tid; i < 256; i += NT) {
        if (i < 64)       ((float*)sA)[i]        = ((const float*)g_A)[i];
        else if (i < 72)  scc[i - 64]            = g_c[i - 64];
        else if (i < 136) ((float*)swv)[i - 72]  = ca_w_in[16 * EE + (i - 72)];
        else if (i < 144) sbv[i - 136]           = ca_b_in[16 + (i - 136)];
        else if (i < 208) ((float*)swo)[i - 144] = ca_w_out[i - 144];
        else if (i < 216) sbo[i - 208]           = ca_b_out[i - 208];
        else if (i < 232) srb1[i - 216]          = r_b1[i - 216];
        else if (i < 248) srw2[i - 232]          = r_w2[i - 232];
        else if (i == 248) sb2                   = r_b2[0];
    }
#pragma unroll
    for (int i = tid; i < 512; i += NT) srw1[(i >> 5) * 33 + (i & 31)] = r_w1[i];
    __syncthreads();

    // ---- P1+P3: scores -> exp (no max; bounded) -> partials -> reduce ----
#pragma unroll
    for (int fh = 0; fh < 8; fh++) {
        float wgt[NR];
#pragma unroll
        for (int r = 0; r < NR; r++) {
            float a = scc[fh];
#pragma unroll
            for (int e = 0; e < 8; e++) a += sA[fh][e] * xr[r][e];
            wgt[r] = __expf(a);
        }
        float q[9];
#pragma unroll
        for (int e = 0; e < 8; e++) {
            float a = wgt[0] * xr[0][e];
#pragma unroll
            for (int r = 1; r < NR; r++) a = fmaf(wgt[r], xr[r][e], a);
            q[e] = a;
        }
        q[8] = (wgt[0] + wgt[1]) + (wgt[2] + wgt[3]);
        float rr = warp_reduce9(q);
        if (wvalid) pacc[w][fh * 12 + start] = rr;
    }
    __syncthreads();

    // ---- combine 4 warp-partials: thread t<72 handles one entry ----
    if (tid < 72) {
        int fh = tid / 9, k = tid - fh * 9;
        red[tid] = (pacc[0][fh * 12 + k] + pacc[1][fh * 12 + k])
                 + (pacc[2][fh * 12 + k] + pacc[3][fh * 12 + k]);
    }
    __syncthreads();

    // ---- P5: warp 0: ctx -> Q_cross ----
    if (w == 0) {
        {
            int f = lane >> 3, r = lane & 7;
            int fh = f * 2 + (r >> 2);
            float inv = 1.0f / red[fh * 9 + 8];
            float a = 0.f;
#pragma unroll
            for (int e = 0; e < 8; e++) a += red[fh * 9 + e] * swv[r][e];
            sctx[lane] = a * inv + sbv[r];
        }
        __syncwarp();
        {
            int f = lane >> 3, ep = lane & 7;
            float a = sbo[ep];
#pragma unroll
            for (int e = 0; e < 8; e++) a += sctx[f * 8 + e] * swo[ep][e];
            sqc[f * 8 + ep] = a;
        }
    }
    __syncthreads();

    // ---- P6+P7: similarity -> gmem; exp -> partials -> reduce ----
    float* __restrict__ simo = sim + (size_t)b * (FF * SS);
#pragma unroll
    for (int f = 0; f < 4; f++) {
        float wgt[NR];
#pragma unroll
        for (int r = 0; r < NR; r++) {
            float a = 0.f;
#pragma unroll
            for (int e = 0; e < 8; e++) a += sqc[f * 8 + e] * xr[r][e];
            simo[f * SS + tid + NT * r] = a;
            wgt[r] = __expf(a);
        }
        float q[9];
#pragma unroll
        for (int e = 0; e < 8; e++) {
            float a = wgt[0] * xr[0][e];
#pragma unroll
            for (int r = 1; r < NR; r++) a = fmaf(wgt[r], xr[r][e], a);
            q[e] = a;
        }
        q[8] = (wgt[0] + wgt[1]) + (wgt[2] + wgt[3]);
        float rr = warp_reduce9(q);
        if (wvalid) pacc[w][f * 12 + start] = rr;
    }
    __syncthreads();

    // ---- combine: thread t<36 handles one entry ----
    if (tid < 36) {
        int f = tid / 9, k = tid - f * 9;
        red[tid] = (pacc[0][f * 12 + k] + pacc[1][f * 12 + k])
                 + (pacc[2][f * 12 + k] + pacc[3][f * 12 + k]);
    }
    __syncthreads();

    // ---- P8: warp 0: final factors + MLP head ----
    if (w == 0) {
        {
            int f = lane >> 3, e = lane & 7;
            sfin[lane] = red[f * 9 + e] / red[f * 9 + 8];
        }
        __syncwarp();
        float v = 0.f;
        if (lane < 16) {
            float a = srb1[lane];
#pragma unroll
            for (int j = 0; j < 32; j++) a += sfin[j] * srw1[lane * 33 + j];
            v = fmaxf(a, 0.f) * srw2[lane];
        }
#pragma unroll
        for (int o = 16; o > 0; o >>= 1) v += __shfl_xor_sync(~0u, v, o);
        if (lane == 0) outv[b] = v + sb2;
    }
}

extern "C" void kernel_launch(void* const* d_in, const int* in_sizes, int n_in,
                              void* d_out, int out_size) {
    const float* x        = (const float*)d_in[0];
    const float* Q        = (const float*)d_in[1];
    const float* sa_w_in  = (const float*)d_in[2];
    const float* sa_b_in  = (const float*)d_in[3];
    const float* sa_w_out = (const float*)d_in[4];
    const float* sa_b_out = (const float*)d_in[5];
    const float* ca_w_in  = (const float*)d_in[6];
    const float* ca_b_in  = (const float*)d_in[7];
    const float* ca_w_out = (const float*)d_in[8];
    const float* ca_b_out = (const float*)d_in[9];
    const float* r_w1     = (const float*)d_in[10];
    const float* r_b1     = (const float*)d_in[11];
    const float* r_w2     = (const float*)d_in[12];
    const float* r_b2     = (const float*)d_in[13];

    int B = in_sizes[0] / (SS * EE);
    float* outv = (float*)d_out;          // [B] first return value
    float* sim  = outv + B;               // [B, F, S] second return value

    precompute_kernel<<<1, 1>>>(Q, sa_w_in, sa_b_in, sa_w_out, sa_b_out, ca_w_in, ca_b_in);
    afs_main_kernel<<<B, NT>>>(x, r_b2, outv, sim,
                               ca_w_in, ca_b_in, ca_w_out, ca_b_out,
                               r_w1, r_b1, r_w2);
}